// round 2
// baseline (speedup 1.0000x reference)
#include <cuda_runtime.h>
#include <cstdint>

#define NH    218
#define NSUB  47524      // 218*218
#define NROWS 64         // B * C_OUT * C_IN = 2*8*4

// ---------------- device globals (no allocations allowed) ----------------
__device__ float2   g_Wn[8][4][12][24];   // [-2*W] paired over (p=2pp, p=2pp+1)
__device__ float    g_c2[8][4];           // ||Kp||^2+||Rp||^2+||Cp||^2 (perm-invariant)
__device__ unsigned g_rowmax_u[NROWS];
__device__ float    g_rowmax_f[NROWS];
__device__ float    g_rowsum[NROWS];
__device__ float    g_sims[(size_t)NROWS * NSUB];   // 12.2 MB scratch

__constant__ unsigned char c_P[24][4] = {
  {0,1,2,3},{0,1,3,2},{0,2,1,3},{0,2,3,1},{0,3,1,2},{0,3,2,1},
  {1,0,2,3},{1,0,3,2},{1,2,0,3},{1,2,3,0},{1,3,0,2},{1,3,2,0},
  {2,0,1,3},{2,0,3,1},{2,1,0,3},{2,1,3,0},{2,3,0,1},{2,3,1,0},
  {3,0,1,2},{3,0,2,1},{3,1,0,2},{3,1,2,0},{3,2,0,1},{3,2,1,0}
};

// ---------------- prep: expand permuted weights, init reductions ----------
__global__ void prep_kernel(const float* __restrict__ ks,
                            const float* __restrict__ kr,
                            const float* __restrict__ kc) {
    int tid = threadIdx.x;
    if (tid < NROWS) { g_rowmax_u[tid] = 0u; g_rowsum[tid] = 0.0f; }
    if (tid < 32) {
        int oi = tid;
        float s = 0.0f;
        const float* a = ks + oi * 16;
        #pragma unroll
        for (int j = 0; j < 16; j++) s += a[j] * a[j];
        const float* r = kr + oi * 4;
        const float* c = kc + oi * 4;
        #pragma unroll
        for (int j = 0; j < 4; j++) { s += r[j] * r[j]; s += c[j] * c[j]; }
        ((float*)g_c2)[oi] = s;
    }
    // 8*4*24 perms * 24 components = 18432 weight entries
    for (int e = tid; e < 8 * 4 * 24 * 24; e += blockDim.x) {
        int c  = e % 24;
        int t  = e / 24;
        int p  = t % 24;
        int oi = t / 24;
        float val;
        if (c < 16) {
            int a = c >> 2, bb = c & 3;
            val = ks[oi * 16 + (int)c_P[p][a] * 4 + (int)c_P[p][bb]];
        } else if (c < 20) {
            val = kr[oi * 4 + (int)c_P[p][c - 16]];
        } else {
            val = kc[oi * 4 + (int)c_P[p][c - 20]];
        }
        // g_Wn[o][i][p>>1][c], component (p&1), holds -2*val
        ((float*)g_Wn)[(oi * 12 + (p >> 1)) * 48 + c * 2 + (p & 1)] = -2.0f * val;
    }
}

// ---------------- h_mean: closed form over feature weights ----------------
__global__ void hmean_kernel(const float* __restrict__ feats, float* __restrict__ out) {
    int b = blockIdx.x, f = threadIdx.x;
    float acc = 0.0f;
    for (int n = 0; n < 224; n++) {
        int lo = (n >= NH) ? ((n - (NH - 2)) >> 1) : 0;   // ceil((n-217)/2)
        int hi = min(3, n >> 1);
        float w = (float)(hi - lo + 1);
        acc += w * feats[(b * 224 + n) * 128 + f];
    }
    out[b * 128 + f] = acc * (2.0f / (float)NH);
}

// ---------------- sims: packed-f32x2 distance + min over perms ------------
__global__ void __launch_bounds__(256, 2)
sims_kernel(const float* __restrict__ graph, const float* __restrict__ types) {
    __shared__ __align__(16) float2 sw[4][4][12][24];  // [oLocal][i][pp][c]
    __shared__ float    sc2[16];
    __shared__ unsigned smax[NROWS];

    int tid   = threadIdx.x;
    int b     = blockIdx.y;
    int oBase = blockIdx.z * 4;

    {
        const float2* src = ((const float2*)g_Wn) + (size_t)oBase * 4 * 12 * 24;
        float2* dst = &sw[0][0][0][0];
        for (int e = tid; e < 4 * 4 * 12 * 24; e += 256) dst[e] = src[e];
        if (tid < 16) sc2[tid] = ((const float*)g_c2)[oBase * 4 + tid];
        if (tid < NROWS) smax[tid] = 0u;
    }
    __syncthreads();

    int  s     = blockIdx.x * 256 + tid;
    bool valid = s < NSUB;
    int  scl   = valid ? s : (NSUB - 1);
    int  h1    = scl / NH;
    int  h2    = scl - h1 * NH;

    #pragma unroll 1
    for (int i = 0; i < 4; i++) {
        // gather x = [sub(16) | row_types(4) | col_types(4)]
        float xv[24];
        const float* gp = graph + (((b * 4 + i) * 224) + h1) * 224 + h2;
        #pragma unroll
        for (int a = 0; a < 4; a++) {
            const float* rp = gp + (2 * a) * 224;
            #pragma unroll
            for (int bb = 0; bb < 4; bb++) xv[a * 4 + bb] = rp[2 * bb];
        }
        const float* tp = types + (b * 4 + i) * 224;
        #pragma unroll
        for (int a = 0; a < 4; a++) {
            xv[16 + a] = tp[h1 + 2 * a];
            xv[20 + a] = tp[h2 + 2 * a];
        }
        float x2 = 0.0f;
        #pragma unroll
        for (int c = 0; c < 24; c++) x2 = fmaf(xv[c], xv[c], x2);

        // duplicate x into packed f32x2 registers
        unsigned long long xd[24];
        #pragma unroll
        for (int c = 0; c < 24; c++) {
            unsigned u = __float_as_uint(xv[c]);
            asm("mov.b64 %0, {%1, %2};" : "=l"(xd[c]) : "r"(u), "r"(u));
        }

        #pragma unroll 1
        for (int o = 0; o < 4; o++) {
            float initf = sc2[o * 4 + i] + x2;
            unsigned long long init;
            {
                unsigned u = __float_as_uint(initf);
                asm("mov.b64 %0, {%1, %2};" : "=l"(init) : "r"(u), "r"(u));
            }
            float m = 3.4e38f;
            const ulonglong2* wbase = (const ulonglong2*)&sw[o][i][0][0];
            #pragma unroll
            for (int pp = 0; pp < 12; pp += 2) {
                unsigned long long acc0 = init, acc1 = init;
                const ulonglong2* w0 = wbase + pp * 12;
                const ulonglong2* w1 = wbase + (pp + 1) * 12;
                #pragma unroll
                for (int cc = 0; cc < 12; cc++) {
                    ulonglong2 wa = w0[cc];
                    ulonglong2 wb = w1[cc];
                    asm("fma.rn.f32x2 %0, %1, %2, %0;" : "+l"(acc0) : "l"(xd[2*cc]),   "l"(wa.x));
                    asm("fma.rn.f32x2 %0, %1, %2, %0;" : "+l"(acc0) : "l"(xd[2*cc+1]), "l"(wa.y));
                    asm("fma.rn.f32x2 %0, %1, %2, %0;" : "+l"(acc1) : "l"(xd[2*cc]),   "l"(wb.x));
                    asm("fma.rn.f32x2 %0, %1, %2, %0;" : "+l"(acc1) : "l"(xd[2*cc+1]), "l"(wb.y));
                }
                float l0, h0, l1, hh1;
                asm("mov.b64 {%0, %1}, %2;" : "=f"(l0), "=f"(h0)  : "l"(acc0));
                asm("mov.b64 {%0, %1}, %2;" : "=f"(l1), "=f"(hh1) : "l"(acc1));
                m = fminf(m, fminf(fminf(l0, h0), fminf(l1, hh1)));
            }

            int row = b * 32 + (oBase + o) * 4 + i;
            if (valid) g_sims[(size_t)row * NSUB + s] = m;
            unsigned key = 0u;
            if (valid) {
                unsigned u = __float_as_uint(m);
                key = (u & 0x80000000u) ? ~u : (u | 0x80000000u);
            }
            unsigned kw = __reduce_max_sync(0xffffffffu, key);
            if ((tid & 31) == 0) atomicMax(&smax[row], kw);
        }
    }

    __syncthreads();
    if (tid < NROWS && smax[tid]) atomicMax(&g_rowmax_u[tid], smax[tid]);
}

// ---------------- softmax passes -----------------------------------------
__global__ void finmax_kernel() {
    int t = threadIdx.x;
    if (t < NROWS) {
        unsigned u = g_rowmax_u[t];
        g_rowmax_f[t] = (u & 0x80000000u) ? __uint_as_float(u & 0x7fffffffu)
                                          : __uint_as_float(~u);
    }
}

__global__ void sumexp_kernel() {
    int row = blockIdx.y;
    float mx = g_rowmax_f[row];
    const float* sp = g_sims + (size_t)row * NSUB;
    float acc = 0.0f;
    int base = blockIdx.x * (256 * 8) + threadIdx.x;
    #pragma unroll
    for (int j = 0; j < 8; j++) {
        int s = base + j * 256;
        if (s < NSUB) acc += __expf(sp[s] - mx);
    }
    #pragma unroll
    for (int off = 16; off; off >>= 1) acc += __shfl_xor_sync(0xffffffffu, acc, off);
    __shared__ float ws[8];
    if ((threadIdx.x & 31) == 0) ws[threadIdx.x >> 5] = acc;
    __syncthreads();
    if (threadIdx.x < 8) {
        float v = ws[threadIdx.x];
        #pragma unroll
        for (int off = 4; off; off >>= 1) v += __shfl_xor_sync(0xffu, v, off);
        if (threadIdx.x == 0) atomicAdd(&g_rowsum[row], v);
    }
}

__global__ void writeout_kernel(float* __restrict__ out) {
    int row = blockIdx.y;
    float mx  = g_rowmax_f[row];
    float inv = 1.0f / g_rowsum[row];
    const float* sp = g_sims + (size_t)row * NSUB;
    float* op = out + 256 + (size_t)row * NSUB;
    int base = blockIdx.x * (256 * 4) + threadIdx.x;
    #pragma unroll
    for (int j = 0; j < 4; j++) {
        int s = base + j * 256;
        if (s < NSUB)
            op[s] = (1.0f - __expf(sp[s] - mx) * inv) * (1.0f / (float)NSUB);
    }
}

// ---------------- launch ---------------------------------------------------
extern "C" void kernel_launch(void* const* d_in, const int* in_sizes, int n_in,
                              void* d_out, int out_size) {
    const float* graph    = (const float*)d_in[0];
    const float* types    = (const float*)d_in[1];
    const float* features = (const float*)d_in[2];
    const float* ks       = (const float*)d_in[3];
    const float* kr       = (const float*)d_in[4];
    const float* kc       = (const float*)d_in[5];
    float* out = (float*)d_out;

    prep_kernel<<<1, 256>>>(ks, kr, kc);
    hmean_kernel<<<2, 128>>>(features, out);
    sims_kernel<<<dim3((NSUB + 255) / 256, 2, 2), 256>>>(graph, types);
    finmax_kernel<<<1, 64>>>();
    sumexp_kernel<<<dim3((NSUB + 2047) / 2048, NROWS), 256>>>();
    writeout_kernel<<<dim3((NSUB + 1023) / 1024, NROWS), 256>>>(out);
}

// round 4
// speedup vs baseline: 1.2293x; 1.2293x over previous
#include <cuda_runtime.h>
#include <cstdint>
#include <cfloat>

#define NH    218
#define NSUB  47524      // 218*218
#define NROWS 64         // B * C_OUT * C_IN = 2*8*4

// ---------------- device globals (no allocations allowed) ----------------
__device__ __align__(16) float2 g_Ws[32 * 12 * 16];   // [-2*Kstruct] packed perm-pairs: [o*4+i][pp][c16]
__device__ float    g_c2[32];                          // ||K||^2+||R||^2+||C||^2 per (o*4+i)
__device__ float2   g_rp[2 * 4 * 8 * 12 * 218];        // rpart: [b][i][o][pp][h1] packed perm-pairs
__device__ float2   g_cp[2 * 4 * 8 * 12 * 218];        // cpart: [b][i][o][pp][h2]
__device__ unsigned g_rowmax_u[NROWS];
__device__ float    g_rowsum[NROWS];
__device__ float    g_sims[(size_t)NROWS * NSUB];      // 12.2 MB scratch

__constant__ unsigned char c_P[24][4] = {
  {0,1,2,3},{0,1,3,2},{0,2,1,3},{0,2,3,1},{0,3,1,2},{0,3,2,1},
  {1,0,2,3},{1,0,3,2},{1,2,0,3},{1,2,3,0},{1,3,0,2},{1,3,2,0},
  {2,0,1,3},{2,0,3,1},{2,1,0,3},{2,1,3,0},{2,3,0,1},{2,3,1,0},
  {3,0,1,2},{3,0,2,1},{3,1,0,2},{3,1,2,0},{3,2,0,1},{3,2,1,0}
};

// ---------------- packed f32x2 helpers -----------------------------------
__device__ __forceinline__ unsigned long long dup2(float f) {
    unsigned long long r; unsigned u = __float_as_uint(f);
    asm("mov.b64 %0, {%1, %1};" : "=l"(r) : "r"(u));
    return r;
}
__device__ __forceinline__ unsigned long long add2(unsigned long long a, unsigned long long b) {
    unsigned long long r;
    asm("add.rn.f32x2 %0, %1, %2;" : "=l"(r) : "l"(a), "l"(b));
    return r;
}
#define FMA2(acc, x, w) asm("fma.rn.f32x2 %0, %1, %2, %0;" : "+l"(acc) : "l"(x), "l"(w))

// ---------------- fused prep: weights, c2, rp/cp tables, h_mean, inits ----
__global__ void prep_all_kernel(const float* __restrict__ types,
                                const float* __restrict__ feats,
                                const float* __restrict__ ks,
                                const float* __restrict__ kr,
                                const float* __restrict__ kc,
                                float* __restrict__ out) {
    int bid = blockIdx.x, tid = threadIdx.x;
    if (bid == 0) {
        if (tid < NROWS) { g_rowmax_u[tid] = 0u; g_rowsum[tid] = 0.0f; }
        if (tid < 32) {
            int oi = tid; float s = 0.0f;
            const float* a = ks + oi * 16;
            #pragma unroll
            for (int j = 0; j < 16; j++) s += a[j] * a[j];
            const float* r = kr + oi * 4; const float* c = kc + oi * 4;
            #pragma unroll
            for (int j = 0; j < 4; j++) { s += r[j] * r[j]; s += c[j] * c[j]; }
            g_c2[oi] = s;
        }
        // struct weights: 32 oi * 24 p * 16 c
        for (int e = tid; e < 32 * 24 * 16; e += blockDim.x) {
            int c = e & 15; int t = e >> 4;
            int p = t % 24; int oi = t / 24;
            int a = c >> 2, bb = c & 3;
            float val = ks[oi * 16 + (int)c_P[p][a] * 4 + (int)c_P[p][bb]];
            ((float*)g_Ws)[((oi * 12 + (p >> 1)) * 16 + c) * 2 + (p & 1)] = -2.0f * val;
        }
    } else if (bid <= 2) {
        // h_mean closed form
        int b = bid - 1;
        if (tid < 128) {
            float acc = 0.0f;
            for (int n = 0; n < 224; n++) {
                int lo = (n >= NH) ? ((n - (NH - 2)) >> 1) : 0;
                int hi = min(3, n >> 1);
                acc += (float)(hi - lo + 1) * feats[(b * 224 + n) * 128 + tid];
            }
            out[b * 128 + tid] = acc * (2.0f / (float)NH);
        }
    } else {
        // rp/cp tables for (b, h)
        int idx = bid - 3;
        int b = idx / NH, h = idx - b * NH;
        for (int e = tid; e < 768; e += blockDim.x) {
            int p = e % 24; int o = (e / 24) & 7; int i = e / 192;
            const float* tp = types + (b * 4 + i) * 224 + h;
            float t0 = tp[0], t1 = tp[2], t2 = tp[4], t3 = tp[6];
            float t2s = t0 * t0 + t1 * t1 + t2 * t2 + t3 * t3;
            const float* krp = kr + (o * 4 + i) * 4;
            const float* kcp = kc + (o * 4 + i) * 4;
            float rd = t0 * krp[c_P[p][0]] + t1 * krp[c_P[p][1]] + t2 * krp[c_P[p][2]] + t3 * krp[c_P[p][3]];
            float cd = t0 * kcp[c_P[p][0]] + t1 * kcp[c_P[p][1]] + t2 * kcp[c_P[p][2]] + t3 * kcp[c_P[p][3]];
            size_t lin = (size_t)(((b * 4 + i) * 8 + o) * 12 + (p >> 1)) * NH + h;
            ((float*)g_rp)[lin * 2 + (p & 1)] = t2s - 2.0f * rd;
            ((float*)g_cp)[lin * 2 + (p & 1)] = t2s - 2.0f * cd;
        }
    }
}

// ---------------- sims: one block per h1 row ------------------------------
// block = 224 threads (h2 = tid, lanes >= 218 masked), grid = (218, B, 2)
__global__ void __launch_bounds__(224, 3)
sims_kernel(const float* __restrict__ graph) {
    __shared__ __align__(16) float2 sw[16 * 12 * 16];   // [oLocal*4+i][pp][c16]  (24.6 KB)
    __shared__ float2   srp[192];                       // rpart for this h1: [(i*4+oL)*12+pp]
    __shared__ float    sc2s[16];
    __shared__ unsigned smax[16];

    int tid   = threadIdx.x;
    int b     = blockIdx.y;
    int oBase = blockIdx.z * 4;
    int h1    = blockIdx.x;           // uniform for the whole block

    // stage struct weights (float4 copies) + rpart for this h1
    {
        const float4* src = ((const float4*)g_Ws) + (size_t)oBase * 4 * 12 * 8;
        float4* dst = (float4*)sw;
        for (int e = tid; e < 16 * 12 * 8; e += 224) dst[e] = src[e];
        if (tid < 16) { sc2s[tid] = g_c2[oBase * 4 + tid]; smax[tid] = 0u; }
        if (tid < 192) {
            int i = tid / 48, oL = (tid / 12) & 3, pp = tid % 12;
            srp[tid] = g_rp[(size_t)((b * 32 + i * 8 + oBase + oL) * 12 + pp) * NH + h1];
        }
    }
    __syncthreads();

    int  h2    = tid;
    bool valid = h2 < NH;
    int  h2c   = valid ? h2 : (NH - 1);
    int  s     = h1 * NH + h2c;

    #pragma unroll 1
    for (int i = 0; i < 4; i++) {
        float xv[16];
        const float* gp = graph + (((b * 4 + i) * 224) + h1) * 224 + h2c;
        #pragma unroll
        for (int a = 0; a < 4; a++) {
            const float* rp = gp + (2 * a) * 224;
            #pragma unroll
            for (int bb = 0; bb < 4; bb++) xv[a * 4 + bb] = rp[2 * bb];
        }
        float x2 = 0.0f;
        #pragma unroll
        for (int c = 0; c < 16; c++) x2 = fmaf(xv[c], xv[c], x2);

        unsigned long long xd[16];
        #pragma unroll
        for (int c = 0; c < 16; c++) xd[c] = dup2(xv[c]);

        #pragma unroll 1
        for (int o = 0; o < 4; o++) {
            // per-pack row/col parts: rc[pp] = rpart(h1) + cpart(h2), packed over perm pair
            unsigned long long rc[12];
            {
                const unsigned long long* cpg =
                    (const unsigned long long*)(g_cp + (size_t)((b * 32 + i * 8 + oBase + o) * 12) * NH + h2c);
                const unsigned long long* rps =
                    (const unsigned long long*)(srp + (i * 4 + o) * 12);
                #pragma unroll
                for (int pp = 0; pp < 12; pp++)
                    rc[pp] = add2(cpg[(size_t)pp * NH], rps[pp]);
            }
            unsigned long long init2 = dup2(x2 + sc2s[o * 4 + i]);
            float m = FLT_MAX;
            const ulonglong2* wb = (const ulonglong2*)&sw[(o * 4 + i) * 192];
            #pragma unroll
            for (int pp = 0; pp < 12; pp += 2) {
                unsigned long long acc0 = add2(init2, rc[pp]);
                unsigned long long acc1 = add2(init2, rc[pp + 1]);
                const ulonglong2* w0 = wb + pp * 8;
                const ulonglong2* w1 = w0 + 8;
                #pragma unroll
                for (int cc = 0; cc < 8; cc++) {
                    ulonglong2 wa = w0[cc];
                    ulonglong2 wv = w1[cc];
                    FMA2(acc0, xd[2 * cc],     wa.x);
                    FMA2(acc0, xd[2 * cc + 1], wa.y);
                    FMA2(acc1, xd[2 * cc],     wv.x);
                    FMA2(acc1, xd[2 * cc + 1], wv.y);
                }
                float l0, h0, l1, hh1;
                asm("mov.b64 {%0, %1}, %2;" : "=f"(l0), "=f"(h0)  : "l"(acc0));
                asm("mov.b64 {%0, %1}, %2;" : "=f"(l1), "=f"(hh1) : "l"(acc1));
                m = fminf(m, fminf(fminf(l0, h0), fminf(l1, hh1)));
            }

            int row = b * 32 + (oBase + o) * 4 + i;
            if (valid) g_sims[(size_t)row * NSUB + s] = m;
            unsigned key = 0u;
            if (valid) {
                unsigned u = __float_as_uint(m);
                key = (u & 0x80000000u) ? ~u : (u | 0x80000000u);
            }
            unsigned kw = __reduce_max_sync(0xffffffffu, key);
            if ((tid & 31) == 0) atomicMax(&smax[o * 4 + i], kw);
        }
    }

    __syncthreads();
    if (tid < 16 && smax[tid])
        atomicMax(&g_rowmax_u[b * 32 + oBase * 4 + tid], smax[tid]);
}

// ---------------- softmax passes (finmax inlined) -------------------------
__device__ __forceinline__ float decode_max(unsigned u) {
    return (u & 0x80000000u) ? __uint_as_float(u & 0x7fffffffu) : __uint_as_float(~u);
}

__global__ void sumexp_kernel() {
    int row = blockIdx.y;
    float mx = decode_max(g_rowmax_u[row]);
    const float* sp = g_sims + (size_t)row * NSUB;
    float acc = 0.0f;
    int base = blockIdx.x * (256 * 8) + threadIdx.x;
    #pragma unroll
    for (int j = 0; j < 8; j++) {
        int s = base + j * 256;
        if (s < NSUB) acc += __expf(sp[s] - mx);
    }
    #pragma unroll
    for (int off = 16; off; off >>= 1) acc += __shfl_xor_sync(0xffffffffu, acc, off);
    __shared__ float ws[8];
    if ((threadIdx.x & 31) == 0) ws[threadIdx.x >> 5] = acc;
    __syncthreads();
    if (threadIdx.x < 8) {
        float v = ws[threadIdx.x];
        #pragma unroll
        for (int off = 4; off; off >>= 1) v += __shfl_xor_sync(0xffu, v, off);
        if (threadIdx.x == 0) atomicAdd(&g_rowsum[row], v);
    }
}

__global__ void writeout_kernel(float* __restrict__ out) {
    int row = blockIdx.y;
    float mx  = decode_max(g_rowmax_u[row]);
    float inv = 1.0f / g_rowsum[row];
    const float* sp = g_sims + (size_t)row * NSUB;
    float* op = out + 256 + (size_t)row * NSUB;
    int base = blockIdx.x * (256 * 4) + threadIdx.x;
    #pragma unroll
    for (int j = 0; j < 4; j++) {
        int s = base + j * 256;
        if (s < NSUB)
            op[s] = (1.0f - __expf(sp[s] - mx) * inv) * (1.0f / (float)NSUB);
    }
}

// ---------------- launch ---------------------------------------------------
extern "C" void kernel_launch(void* const* d_in, const int* in_sizes, int n_in,
                              void* d_out, int out_size) {
    const float* graph    = (const float*)d_in[0];
    const float* types    = (const float*)d_in[1];
    const float* features = (const float*)d_in[2];
    const float* ks       = (const float*)d_in[3];
    const float* kr       = (const float*)d_in[4];
    const float* kc       = (const float*)d_in[5];
    float* out = (float*)d_out;

    prep_all_kernel<<<3 + 2 * NH, 256>>>(types, features, ks, kr, kc, out);
    sims_kernel<<<dim3(NH, 2, 2), 224>>>(graph);
    sumexp_kernel<<<dim3((NSUB + 2047) / 2048, NROWS), 256>>>();
    writeout_kernel<<<dim3((NSUB + 1023) / 1024, NROWS), 256>>>(out);
}